// round 10
// baseline (speedup 1.0000x reference)
#include <cuda_runtime.h>
#include <math.h>

#define BB 4
#define CC 7
#define HH 512
#define WW 1024
#define HW (HH*WW)            // 524288
#define NID 7
#define NTASK (BB*NID)        // 28
#define NBINS 1024            // e-bins over [0,2]
#define FULLM 0xffffffffu
#define NBLK_A (HW/2048*BB)   // 1024 stageA blocks

// ---- persistent scratch (self-cleaning across graph replays) ----
__device__ float4   g_pack[BB*HW];            // ex, ey, seed, inst(bits)
__device__ unsigned g_hist[NTASK*NBINS*2];    // [task][bin*2 + fg] (224 KB, L2-hot)
__device__ float    g_stat[NTASK*7];          // cnt, sum_xw, sum_yh, s0, s1, s0^2, s1^2
__device__ float    g_batch[BB*3];            // cls_sum, valid_cnt, seed_bg
__device__ float    g_task[NTASK*8];          // cx, cy, sex, sey, varl, present
__device__ float    g_seedfg[NTASK];
__device__ float    g_instl[NTASK];
__device__ unsigned g_semA;                   // last-block-done counters (reset each run)
__device__ unsigned g_semD;

// ---------------- stage A: transforms + per-(b,id) stats; fused stage B ----------------
__global__ __launch_bounds__(256) void stageA(const float* __restrict__ pred,
                                              const int*  __restrict__ inst,
                                              const int*  __restrict__ lab) {
    __shared__ float s_acc[52];   // 7 ids * 7 stats + cls, vcnt, seedbg
    __shared__ bool  sLast;
    int b = blockIdx.y;
    int tid = threadIdx.x;
    int lane = tid & 31;
    if (tid < 52) s_acc[tid] = 0.f;
    __syncthreads();

    const float* pb = pred + b*(CC*HW);
    int base = blockIdx.x*2048;
    float cls = 0.f, vc = 0.f, sbg = 0.f;

    #pragma unroll
    for (int k = 0; k < 8; k++) {
        int pix = base + k*256 + tid;
        float p0 = pb[pix],      p1 = pb[HW+pix],   p2 = pb[2*HW+pix];
        float p3 = pb[3*HW+pix], p4 = pb[4*HW+pix];
        float p5 = pb[5*HW+pix], p6 = pb[6*HW+pix];
        int iv = inst[b*HW+pix];
        int lv = lab [b*HW+pix];
        int w = pix & (WW-1);
        int h = pix >> 10;

        float xw = (2.0f/2047.0f)*(float)w;
        float yh = (1.0f/1023.0f)*(float)h;
        float t0 = __expf(2.f*p0);
        float t1 = __expf(2.f*p1);
        float ex = __fdividef(t0-1.f, t0+1.f) + xw;   // tanh(p0)+xw
        float ey = __fdividef(t1-1.f, t1+1.f) + yh;
        float sd = __fdividef(1.f, 1.f + __expf(-p4));
        float4 P; P.x = ex; P.y = ey; P.z = sd; P.w = __int_as_float(iv);
        g_pack[b*HW+pix] = P;

        if (lv < 2) {
            float m   = fmaxf(p5, p6);
            float lse = m + __logf(__expf(p5-m) + __expf(p6-m));
            float logpt = ((lv == 0) ? p5 : p6) - lse;
            float pt  = __expf(logpt);
            float om  = 1.0f - pt;
            cls -= om*om*logpt;
            vc  += 1.0f;
        }
        if (lv == 0) sbg += sd*sd;

        // partition warp by id; aggregate via hardware REDUX in fixed-point
        unsigned grp = __match_any_sync(FULLM, iv);
        if (iv >= 1) {
            int r1 = __reduce_add_sync(grp, __float2int_rn(xw   *1048576.f)); // 2^20
            int r2 = __reduce_add_sync(grp, __float2int_rn(yh   *1048576.f));
            int r3 = __reduce_add_sync(grp, __float2int_rn(p2   * 262144.f)); // 2^18
            int r4 = __reduce_add_sync(grp, __float2int_rn(p3   * 262144.f));
            int r5 = __reduce_add_sync(grp, __float2int_rn(p2*p2*  16384.f)); // 2^14
            int r6 = __reduce_add_sync(grp, __float2int_rn(p3*p3*  16384.f));
            if (lane == __ffs(grp)-1) {
                float* a = &s_acc[(iv-1)*7];
                atomicAdd(a+0, (float)__popc(grp));
                atomicAdd(a+1, (float)r1 * (1.f/1048576.f));
                atomicAdd(a+2, (float)r2 * (1.f/1048576.f));
                atomicAdd(a+3, (float)r3 * (1.f/262144.f));
                atomicAdd(a+4, (float)r4 * (1.f/262144.f));
                atomicAdd(a+5, (float)r5 * (1.f/16384.f));
                atomicAdd(a+6, (float)r6 * (1.f/16384.f));
            }
        }
    }
    #pragma unroll
    for (int o = 16; o; o >>= 1) {
        cls += __shfl_down_sync(FULLM, cls, o);
        vc  += __shfl_down_sync(FULLM, vc,  o);
        sbg += __shfl_down_sync(FULLM, sbg, o);
    }
    if (lane == 0) {
        atomicAdd(&s_acc[49], cls);
        atomicAdd(&s_acc[50], vc);
        atomicAdd(&s_acc[51], sbg);
    }
    __syncthreads();
    if      (tid < 49) atomicAdd(&g_stat[b*49 + tid], s_acc[tid]);
    else if (tid < 52) atomicAdd(&g_batch[b*3 + tid - 49], s_acc[tid]);

    // ---- last-block-done: fused stage B ----
    __threadfence();
    __syncthreads();
    if (tid == 0) sLast = (atomicAdd(&g_semA, 1u) == NBLK_A-1);
    __syncthreads();
    if (sLast) {
        if (tid < NTASK) {
            int t = tid;
            float cnt  = __ldcg(&g_stat[t*7+0]);
            float s1   = __ldcg(&g_stat[t*7+1]);
            float s2   = __ldcg(&g_stat[t*7+2]);
            float s3   = __ldcg(&g_stat[t*7+3]);
            float s4   = __ldcg(&g_stat[t*7+4]);
            float s5   = __ldcg(&g_stat[t*7+5]);
            float s6   = __ldcg(&g_stat[t*7+6]);
            float pres = (cnt > 0.f) ? 1.f : 0.f;
            float cf   = fmaxf(cnt, 1.f);
            float m0 = s3/cf, m1 = s4/cf;
            g_task[t*8+0] = s1/cf;
            g_task[t*8+1] = s2/cf;
            g_task[t*8+2] = expf(10.f*m0);
            g_task[t*8+3] = expf(10.f*m1);
            g_task[t*8+4] = (s5 - cnt*m0*m0 + s6 - cnt*m1*m1) / (2.f*cf);
            g_task[t*8+5] = pres;
        }
        if (tid == 0) g_semA = 0;    // reset for next replay
    }
}

// ---------------- stage C: 7 ids per block (ILP), match-aggregated REDs ----------------
__global__ __launch_bounds__(256) void stageC() {
    int b = blockIdx.y;
    __shared__ float4 sparam[NID];
    if (threadIdx.x < NID) {
        const float* tk = &g_task[(b*NID+threadIdx.x)*8];
        sparam[threadIdx.x] = make_float4(tk[0], tk[1], tk[2], tk[3]);
    }
    __syncthreads();
    float cx[NID], cy[NID], sx[NID], sy[NID];
    #pragma unroll
    for (int i = 0; i < NID; i++) {
        float4 q = sparam[i];
        cx[i]=q.x; cy[i]=q.y; sx[i]=q.z; sy[i]=q.w;
    }
    unsigned* hb = g_hist + b*NID*NBINS*2;
    float sfg[NID] = {0.f,0.f,0.f,0.f,0.f,0.f,0.f};
    const float4* pk = g_pack + b*HW + blockIdx.x*2048 + threadIdx.x;
    int lane = threadIdx.x & 31;

    #pragma unroll
    for (int k = 0; k < 8; k++) {
        float4 P = pk[k*256];
        int iv = __float_as_int(P.w);
        unsigned key[NID];
        // phase 1: pure compute, 7 independent chains (ILP)
        #pragma unroll
        for (int i = 0; i < NID; i++) {
            float dx = P.x - cx[i], dy = P.y - cy[i];
            float d  = __expf(-(dx*dx*sx[i] + dy*dy*sy[i]));
            bool fg  = (iv == i+1);
            float v  = fg ? (1.f - d) : d;              // e = 2v
            int bin  = min((int)(v * (float)NBINS), NBINS-1);
            key[i] = ((unsigned)bin << 1) | (fg ? 1u : 0u);
            float df = P.z - d;
            sfg[i] += fg ? df*df : 0.f;
        }
        // phase 2: warp-aggregated atomics (fewer RED lanes at 1024 bins)
        #pragma unroll
        for (int i = 0; i < NID; i++) {
            unsigned same = __match_any_sync(FULLM, key[i]);
            if (lane == __ffs(same)-1)
                atomicAdd(hb + i*(NBINS*2) + key[i], (unsigned)__popc(same));
        }
    }
    // reduce sfg[7] across block
    __shared__ float sred[NID][8];
    #pragma unroll
    for (int i = 0; i < NID; i++) {
        float s = sfg[i];
        #pragma unroll
        for (int o = 16; o; o >>= 1) s += __shfl_down_sync(FULLM, s, o);
        if (lane == 0) sred[i][threadIdx.x >> 5] = s;
    }
    __syncthreads();
    if (threadIdx.x < NID) {
        float s = 0.f;
        #pragma unroll
        for (int w = 0; w < 8; w++) s += sred[threadIdx.x][w];
        atomicAdd(&g_seedfg[b*NID + threadIdx.x], s);
    }
}

// ---------------- stage D: Lovász scan + fused combine + self-clean ----------------
__global__ __launch_bounds__(256) void stageD(float* __restrict__ out) {
    int t = blockIdx.x;
    int tid = threadIdx.x;
    int lane = tid & 31, warp = tid >> 5;
    __shared__ bool sLast;
    bool present = (g_task[t*8+5] != 0.f);

    if (present) {
        uint2* hh = (uint2*)(g_hist + t*(NBINS*2));   // .x=bg .y=fg
        const int BPT = NBINS/256;    // 4 bins/thread, descending chunk
        int hi = NBINS-1 - tid*BPT;

        unsigned lf = 0, lt = 0;
        #pragma unroll
        for (int j = 0; j < BPT; j++) {
            uint2 c = hh[hi - j];
            lf += c.y; lt += c.x + c.y;
        }

        __shared__ unsigned sWF[8], sWT[8];
        unsigned incF = lf, incT = lt;
        #pragma unroll
        for (int o = 1; o < 32; o <<= 1) {
            unsigned vF = __shfl_up_sync(FULLM, incF, o);
            unsigned vT = __shfl_up_sync(FULLM, incT, o);
            if (lane >= o) { incF += vF; incT += vT; }
        }
        if (lane == 31) { sWF[warp] = incF; sWT[warp] = incT; }
        __syncthreads();
        if (warp == 0 && lane < 8) {
            unsigned aF = sWF[lane], aT = sWT[lane];
            #pragma unroll
            for (int o = 1; o < 8; o <<= 1) {
                unsigned vF = __shfl_up_sync(0xffu, aF, o);
                unsigned vT = __shfl_up_sync(0xffu, aT, o);
                if (lane >= o) { aF += vF; aT += vT; }
            }
            sWF[lane] = aF; sWT[lane] = aT;
        }
        __syncthreads();
        unsigned F = (warp ? sWF[warp-1] : 0u) + incF - lf;
        unsigned T = (warp ? sWT[warp-1] : 0u) + incT - lt;

        float G = (float)sWF[7];      // exact fg total (< 2^24)
        float jprev = 1.f - (G - (float)F) / (G + (float)(T - F));
        float loss = 0.f;
        #pragma unroll
        for (int j = 0; j < BPT; j++) {
            int bin = hi - j;
            uint2 cc = hh[bin];
            hh[bin] = make_uint2(0u, 0u);     // self-clean for next replay
            unsigned a = cc.y, c = cc.x + cc.y;
            if (c) {
                F += a; T += c;
                float jnew = 1.f - (G - (float)F) / (G + (float)(T - F));
                float e = ((float)bin + 0.5f) * (2.0f/(float)NBINS);
                loss += e * (jnew - jprev);
                jprev = jnew;
            }
        }
        #pragma unroll
        for (int o = 16; o; o >>= 1) loss += __shfl_down_sync(FULLM, loss, o);
        __shared__ float sL[8];
        if (lane == 0) sL[warp] = loss;
        __syncthreads();
        if (tid == 0) {
            float v = 0.f;
            #pragma unroll
            for (int w = 0; w < 8; w++) v += sL[w];
            g_instl[t] = v;
        }
    } else {
        if (tid == 0) g_instl[t] = 0.f;
    }

    // ---- last-block-done: fused final combine + scratch cleanup ----
    __threadfence();
    __syncthreads();
    if (tid == 0) sLast = (atomicAdd(&g_semD, 1u) == NTASK-1);
    __syncthreads();
    if (sLast) {
        if (tid == 0) {
            float total = 0.f;
            for (int b2 = 0; b2 < BB; b2++) {
                float ps = 0.f, il = 0.f, vl = 0.f, sf = 0.f;
                for (int i = 0; i < NID; i++) {
                    int tt = b2*NID + i;
                    float p = g_task[tt*8+5];
                    ps += p;
                    il += __ldcg(&g_instl[tt]) * p;
                    vl += g_task[tt*8+4] * p;
                    sf += g_seedfg[tt]   * p;
                }
                float obj = fmaxf(ps, 1.f);
                float seed_loss = (g_batch[b2*3+2] + 200.f*sf) / (float)HW;
                float loss_b = il/obj + 10.f*(vl/obj) + seed_loss;
                float cls_b  = g_batch[b2*3+0] / fmaxf(g_batch[b2*3+1], 1.f);
                total += loss_b + cls_b;
            }
            out[0] = total * 0.25f;
            g_semD = 0;                       // reset for next replay
        }
        // zero accumulators for next replay
        if (tid < NTASK*7) g_stat[tid]  = 0.f;
        if (tid < BB*3)    g_batch[tid] = 0.f;
        if (tid < NTASK)   g_seedfg[tid]= 0.f;
    }
}

extern "C" void kernel_launch(void* const* d_in, const int* in_sizes, int n_in,
                              void* d_out, int out_size) {
    const float* pred = (const float*)d_in[0];
    const int*   inst = (const int*)  d_in[1];
    const int*   lab  = (const int*)  d_in[2];
    float* out = (float*)d_out;

    stageA <<<dim3(HW/2048, BB), 256>>>(pred, inst, lab);
    stageC <<<dim3(HW/2048, BB), 256>>>();
    stageD <<<NTASK, 256>>>(out);
}

// round 11
// speedup vs baseline: 1.9267x; 1.9267x over previous
#include <cuda_runtime.h>
#include <math.h>

#define BB 4
#define CC 7
#define HH 512
#define WW 1024
#define HW (HH*WW)            // 524288
#define NID 7
#define NTASK (BB*NID)        // 28
#define NBINS 1024            // e-bins over [0,2]
#define FULLM 0xffffffffu
#define NBLK_A (HW/2048*BB)   // 1024 stageA blocks

// ---- persistent scratch (self-cleaning across graph replays) ----
__device__ float4   g_pack[BB*HW];            // ex, ey, seed, inst(bits)
__device__ unsigned g_hist[NTASK*NBINS*2];    // [task][bin*2 + fg] (224 KB, L2-hot)
__device__ float    g_stat[NTASK*7];          // cnt, sum_xw, sum_yh, s0, s1, s0^2, s1^2
__device__ float    g_batch[BB*3];            // cls_sum, valid_cnt, seed_bg
__device__ float    g_task[NTASK*8];          // cx, cy, sex, sey, varl, present
__device__ float    g_seedfg[NTASK];
__device__ float    g_instl[NTASK];
__device__ unsigned g_semA;                   // last-block-done counters (reset each run)
__device__ unsigned g_semD;

// ---------------- stage A: transforms + per-(b,id) stats; fused stage B ----------------
__global__ __launch_bounds__(256) void stageA(const float* __restrict__ pred,
                                              const int*  __restrict__ inst,
                                              const int*  __restrict__ lab) {
    __shared__ float s_acc[52];   // 7 ids * 7 stats + cls, vcnt, seedbg
    __shared__ bool  sLast;
    int b = blockIdx.y;
    int tid = threadIdx.x;
    int lane = tid & 31;
    if (tid < 52) s_acc[tid] = 0.f;
    __syncthreads();

    const float* pb = pred + b*(CC*HW);
    int base = blockIdx.x*2048;
    float cls = 0.f, vc = 0.f, sbg = 0.f;

    #pragma unroll
    for (int k = 0; k < 8; k++) {
        int pix = base + k*256 + tid;
        float p0 = __ldcs(&pb[pix]);
        float p1 = __ldcs(&pb[HW+pix]);
        float p2 = __ldcs(&pb[2*HW+pix]);
        float p3 = __ldcs(&pb[3*HW+pix]);
        float p4 = __ldcs(&pb[4*HW+pix]);
        float p5 = __ldcs(&pb[5*HW+pix]);
        float p6 = __ldcs(&pb[6*HW+pix]);
        int iv = __ldcs(&inst[b*HW+pix]);
        int lv = __ldcs(&lab [b*HW+pix]);
        int w = pix & (WW-1);
        int h = pix >> 10;

        float xw = (2.0f/2047.0f)*(float)w;
        float yh = (1.0f/1023.0f)*(float)h;
        float t0 = __expf(2.f*p0);
        float t1 = __expf(2.f*p1);
        float ex = __fdividef(t0-1.f, t0+1.f) + xw;   // tanh(p0)+xw
        float ey = __fdividef(t1-1.f, t1+1.f) + yh;
        float sd = __fdividef(1.f, 1.f + __expf(-p4));
        float4 P; P.x = ex; P.y = ey; P.z = sd; P.w = __int_as_float(iv);
        g_pack[b*HW+pix] = P;

        if (lv < 2) {
            float m   = fmaxf(p5, p6);
            float lse = m + __logf(__expf(p5-m) + __expf(p6-m));
            float logpt = ((lv == 0) ? p5 : p6) - lse;
            float pt  = __expf(logpt);
            float om  = 1.0f - pt;
            cls -= om*om*logpt;
            vc  += 1.0f;
        }
        if (lv == 0) sbg += sd*sd;

        // partition warp by id; aggregate via hardware REDUX in fixed-point
        unsigned grp = __match_any_sync(FULLM, iv);
        if (iv >= 1) {
            int r1 = __reduce_add_sync(grp, __float2int_rn(xw   *1048576.f)); // 2^20
            int r2 = __reduce_add_sync(grp, __float2int_rn(yh   *1048576.f));
            int r3 = __reduce_add_sync(grp, __float2int_rn(p2   * 262144.f)); // 2^18
            int r4 = __reduce_add_sync(grp, __float2int_rn(p3   * 262144.f));
            int r5 = __reduce_add_sync(grp, __float2int_rn(p2*p2*  16384.f)); // 2^14
            int r6 = __reduce_add_sync(grp, __float2int_rn(p3*p3*  16384.f));
            if (lane == __ffs(grp)-1) {
                float* a = &s_acc[(iv-1)*7];
                atomicAdd(a+0, (float)__popc(grp));
                atomicAdd(a+1, (float)r1 * (1.f/1048576.f));
                atomicAdd(a+2, (float)r2 * (1.f/1048576.f));
                atomicAdd(a+3, (float)r3 * (1.f/262144.f));
                atomicAdd(a+4, (float)r4 * (1.f/262144.f));
                atomicAdd(a+5, (float)r5 * (1.f/16384.f));
                atomicAdd(a+6, (float)r6 * (1.f/16384.f));
            }
        }
    }
    #pragma unroll
    for (int o = 16; o; o >>= 1) {
        cls += __shfl_down_sync(FULLM, cls, o);
        vc  += __shfl_down_sync(FULLM, vc,  o);
        sbg += __shfl_down_sync(FULLM, sbg, o);
    }
    if (lane == 0) {
        atomicAdd(&s_acc[49], cls);
        atomicAdd(&s_acc[50], vc);
        atomicAdd(&s_acc[51], sbg);
    }
    __syncthreads();
    if      (tid < 49) atomicAdd(&g_stat[b*49 + tid], s_acc[tid]);
    else if (tid < 52) atomicAdd(&g_batch[b*3 + tid - 49], s_acc[tid]);

    // ---- last-block-done: fused stage B ----
    __threadfence();
    __syncthreads();
    if (tid == 0) sLast = (atomicAdd(&g_semA, 1u) == NBLK_A-1);
    __syncthreads();
    if (sLast) {
        if (tid < NTASK) {
            int t = tid;
            float cnt  = __ldcg(&g_stat[t*7+0]);
            float s1   = __ldcg(&g_stat[t*7+1]);
            float s2   = __ldcg(&g_stat[t*7+2]);
            float s3   = __ldcg(&g_stat[t*7+3]);
            float s4   = __ldcg(&g_stat[t*7+4]);
            float s5   = __ldcg(&g_stat[t*7+5]);
            float s6   = __ldcg(&g_stat[t*7+6]);
            float pres = (cnt > 0.f) ? 1.f : 0.f;
            float cf   = fmaxf(cnt, 1.f);
            float m0 = s3/cf, m1 = s4/cf;
            g_task[t*8+0] = s1/cf;
            g_task[t*8+1] = s2/cf;
            g_task[t*8+2] = expf(10.f*m0);
            g_task[t*8+3] = expf(10.f*m1);
            g_task[t*8+4] = (s5 - cnt*m0*m0 + s6 - cnt*m1*m1) / (2.f*cf);
            g_task[t*8+5] = pres;
        }
        if (tid == 0) g_semA = 0;    // reset for next replay
    }
}

// ---------------- stage C: fg exact + bg 1/4-stratified weighted REDs ----------------
__global__ __launch_bounds__(256) void stageC() {
    int b = blockIdx.y;
    __shared__ float4 sparam[8];   // indexed by iv; [0] = zeros
    if (threadIdx.x < 8) {
        if (threadIdx.x == 0) sparam[0] = make_float4(0.f,0.f,0.f,0.f);
        else {
            const float* tk = &g_task[(b*NID + threadIdx.x-1)*8];
            sparam[threadIdx.x] = make_float4(tk[0], tk[1], tk[2], tk[3]);
        }
    }
    __syncthreads();
    float cxr[NID], cyr[NID], sxr[NID], syr[NID];
    #pragma unroll
    for (int i = 0; i < NID; i++) {
        float4 q = sparam[i+1];
        cxr[i]=q.x; cyr[i]=q.y; sxr[i]=q.z; syr[i]=q.w;
    }

    unsigned* hb = g_hist + b*NID*NBINS*2;
    float sfg[NID] = {0.f,0.f,0.f,0.f,0.f,0.f,0.f};
    const float4* pk = g_pack + b*HW + blockIdx.x*2048 + threadIdx.x;
    int lane = threadIdx.x & 31;

    #pragma unroll
    for (int k = 0; k < 8; k++) {
        float4 P = pk[k*256];
        int iv = __float_as_int(P.w);

        // ---- pass 1: this pixel's own id — EXACT fg contribution ----
        if (iv >= 1) {
            float4 q = sparam[iv];              // dynamic LDS.128
            float dx = P.x - q.x, dy = P.y - q.y;
            float d  = __expf(-(dx*dx*q.z + dy*dy*q.w));
            int bin  = min((int)((1.f - d)*(float)NBINS), NBINS-1);
            atomicAdd(hb + (iv-1)*(NBINS*2) + bin*2 + 1, 1u);
            float df = P.z - d;
            float df2 = df*df;
            #pragma unroll
            for (int i = 0; i < NID; i++) sfg[i] += (iv == i+1) ? df2 : 0.f;
        }

        // ---- pass 2: bg histogram, 1/4 stratified (warp-uniform k-phase), weight 4 ----
        #pragma unroll
        for (int i = 0; i < NID; i++) {
            if (((k + i) & 3) != 0) continue;   // compile-time: 2 of 8 iters per id
            if (iv != i+1) {
                float dx = P.x - cxr[i], dy = P.y - cyr[i];
                float d  = __expf(-(dx*dx*sxr[i] + dy*dy*syr[i]));
                int bin  = min((int)(d*(float)NBINS), NBINS-1);
                atomicAdd(hb + i*(NBINS*2) + bin*2, 4u);
            }
        }
    }
    // reduce sfg[7] across block
    __shared__ float sred[NID][8];
    #pragma unroll
    for (int i = 0; i < NID; i++) {
        float s = sfg[i];
        #pragma unroll
        for (int o = 16; o; o >>= 1) s += __shfl_down_sync(FULLM, s, o);
        if (lane == 0) sred[i][threadIdx.x >> 5] = s;
    }
    __syncthreads();
    if (threadIdx.x < NID) {
        float s = 0.f;
        #pragma unroll
        for (int w = 0; w < 8; w++) s += sred[threadIdx.x][w];
        atomicAdd(&g_seedfg[b*NID + threadIdx.x], s);
    }
}

// ---------------- stage D: Lovász scan + fused combine + self-clean ----------------
__global__ __launch_bounds__(256) void stageD(float* __restrict__ out) {
    int t = blockIdx.x;
    int tid = threadIdx.x;
    int lane = tid & 31, warp = tid >> 5;
    __shared__ bool sLast;
    bool present = (g_task[t*8+5] != 0.f);

    uint2* hh = (uint2*)(g_hist + t*(NBINS*2));   // .x=bg(w4) .y=fg
    const int BPT = NBINS/256;    // 4 bins/thread, descending chunk
    int hi = NBINS-1 - tid*BPT;

    // pass 1: chunk sums (also used for self-clean below)
    unsigned lf = 0, lt = 0;
    uint2 cc[BPT];
    #pragma unroll
    for (int j = 0; j < BPT; j++) {
        cc[j] = hh[hi - j];
        hh[hi - j] = make_uint2(0u, 0u);          // always self-clean for next replay
        lf += cc[j].y; lt += cc[j].x + cc[j].y;
    }

    __shared__ unsigned sWF[8], sWT[8];
    unsigned incF = lf, incT = lt;
    #pragma unroll
    for (int o = 1; o < 32; o <<= 1) {
        unsigned vF = __shfl_up_sync(FULLM, incF, o);
        unsigned vT = __shfl_up_sync(FULLM, incT, o);
        if (lane >= o) { incF += vF; incT += vT; }
    }
    if (lane == 31) { sWF[warp] = incF; sWT[warp] = incT; }
    __syncthreads();
    if (warp == 0 && lane < 8) {
        unsigned aF = sWF[lane], aT = sWT[lane];
        #pragma unroll
        for (int o = 1; o < 8; o <<= 1) {
            unsigned vF = __shfl_up_sync(0xffu, aF, o);
            unsigned vT = __shfl_up_sync(0xffu, aT, o);
            if (lane >= o) { aF += vF; aT += vT; }
        }
        sWF[lane] = aF; sWT[lane] = aT;
    }
    __syncthreads();
    unsigned F = (warp ? sWF[warp-1] : 0u) + incF - lf;
    unsigned T = (warp ? sWT[warp-1] : 0u) + incT - lt;

    float G = (float)sWF[7];      // exact fg total
    float loss = 0.f;
    if (present) {
        float jprev = 1.f - (G - (float)F) / (G + (float)(T - F));
        #pragma unroll
        for (int j = 0; j < BPT; j++) {
            int bin = hi - j;
            unsigned a = cc[j].y, c = cc[j].x + cc[j].y;
            if (c) {
                F += a; T += c;
                float jnew = 1.f - (G - (float)F) / (G + (float)(T - F));
                float e = ((float)bin + 0.5f) * (2.0f/(float)NBINS);
                loss += e * (jnew - jprev);
                jprev = jnew;
            }
        }
    }
    #pragma unroll
    for (int o = 16; o; o >>= 1) loss += __shfl_down_sync(FULLM, loss, o);
    __shared__ float sL[8];
    if (lane == 0) sL[warp] = loss;
    __syncthreads();
    if (tid == 0) {
        float v = 0.f;
        #pragma unroll
        for (int w = 0; w < 8; w++) v += sL[w];
        g_instl[t] = present ? v : 0.f;
    }

    // ---- last-block-done: fused final combine, then cleanup (ordered!) ----
    __threadfence();
    __syncthreads();
    if (tid == 0) sLast = (atomicAdd(&g_semD, 1u) == NTASK-1);
    __syncthreads();
    if (sLast) {
        if (tid == 0) {
            float total = 0.f;
            for (int b2 = 0; b2 < BB; b2++) {
                float ps = 0.f, il = 0.f, vl = 0.f, sf = 0.f;
                for (int i = 0; i < NID; i++) {
                    int tt = b2*NID + i;
                    float p = g_task[tt*8+5];
                    ps += p;
                    il += __ldcg(&g_instl[tt]) * p;
                    vl += g_task[tt*8+4] * p;
                    sf += __ldcg(&g_seedfg[tt]) * p;
                }
                float obj = fmaxf(ps, 1.f);
                float seed_loss = (__ldcg(&g_batch[b2*3+2]) + 200.f*sf) / (float)HW;
                float loss_b = il/obj + 10.f*(vl/obj) + seed_loss;
                float cls_b  = __ldcg(&g_batch[b2*3+0]) / fmaxf(__ldcg(&g_batch[b2*3+1]), 1.f);
                total += loss_b + cls_b;
            }
            out[0] = total * 0.25f;
        }
        __syncthreads();   // combine reads MUST complete before zeroing
        if (tid < NTASK*7) g_stat[tid]  = 0.f;
        if (tid < BB*3)    g_batch[tid] = 0.f;
        if (tid < NTASK)   g_seedfg[tid]= 0.f;
        if (tid == 0)      g_semD = 0;
    }
}

extern "C" void kernel_launch(void* const* d_in, const int* in_sizes, int n_in,
                              void* d_out, int out_size) {
    const float* pred = (const float*)d_in[0];
    const int*   inst = (const int*)  d_in[1];
    const int*   lab  = (const int*)  d_in[2];
    float* out = (float*)d_out;

    stageA <<<dim3(HW/2048, BB), 256>>>(pred, inst, lab);
    stageC <<<dim3(HW/2048, BB), 256>>>();
    stageD <<<NTASK, 256>>>(out);
}

// round 13
// speedup vs baseline: 2.4107x; 1.2512x over previous
#include <cuda_runtime.h>
#include <math.h>

#define BB 4
#define CC 7
#define HH 512
#define WW 1024
#define HW (HH*WW)            // 524288
#define NID 7
#define NTASK (BB*NID)        // 28
#define NBINS 1024            // e-bins over [0,2]
#define FULLM 0xffffffffu
#define NBLK_A (HW/2048*BB)   // 1024 stageA blocks

// ---- persistent scratch (self-cleaning across graph replays) ----
__device__ unsigned g_hist[NTASK*NBINS*2];    // [task][bin*2 + fg] (224 KB, L2-hot)
__device__ float    g_stat[NTASK*6];          // cnt, sum_xw, sum_yh, s_p2, s_p3, s_sq
__device__ float    g_batch[BB*3];            // cls_sum, valid_cnt, seed_bg
__device__ float    g_task[NTASK*8];          // cx, cy, sex, sey, varl, present
__device__ float    g_seedfg[NTASK];
__device__ float    g_instl[NTASK];
__device__ unsigned g_semA;                   // last-block-done counters (reset each run)
__device__ unsigned g_semD;

// ---------------- stage A: stats + scalars; fused stage B ----------------
__global__ __launch_bounds__(256) void stageA(const float* __restrict__ pred,
                                              const int*  __restrict__ inst,
                                              const int*  __restrict__ lab) {
    __shared__ float s_acc[45];   // 7 ids * 6 stats + cls, vcnt, seedbg
    __shared__ bool  sLast;
    int b = blockIdx.y;
    int tid = threadIdx.x;
    int lane = tid & 31;
    if (tid < 45) s_acc[tid] = 0.f;
    __syncthreads();

    const float* pb = pred + b*(CC*HW);
    int base = blockIdx.x*2048;
    float cls = 0.f, vc = 0.f, sbg = 0.f;

    #pragma unroll
    for (int it = 0; it < 2; it++) {
        int px0 = base + it*1024 + tid*4;        // 4 consecutive px per thread
        float4 q2v = *(const float4*)&pb[2*HW+px0];
        float4 q3v = *(const float4*)&pb[3*HW+px0];
        float4 q4v = *(const float4*)&pb[4*HW+px0];
        float4 q5v = *(const float4*)&pb[5*HW+px0];
        float4 q6v = *(const float4*)&pb[6*HW+px0];
        int4   iv4 = *(const int4*)&inst[b*HW+px0];
        int4   lv4 = *(const int4*)&lab [b*HW+px0];
        const float* c2 = (const float*)&q2v;
        const float* c5 = (const float*)&q5v;
        const float* c6 = (const float*)&q6v;
        const float* c3 = (const float*)&q3v;
        const float* c4 = (const float*)&q4v;
        const int*   ci = (const int*)&iv4;
        const int*   cl = (const int*)&lv4;
        // one full row (1024 px) per it-iteration: yh is block-uniform here
        float yh = (1.0f/1023.0f)*(float)((base + it*1024) >> 10);

        #pragma unroll
        for (int j = 0; j < 4; j++) {
            float p2 = c2[j], p3 = c3[j], p4 = c4[j], p5 = c5[j], p6 = c6[j];
            int iv = ci[j];
            int lv = cl[j];

            if (lv < 2) {  // focal: lse = max + log(1+exp(-|diff|))
                float dd  = p5 - p6;
                float lse = fmaxf(p5, p6) + __logf(1.f + __expf(-fabsf(dd)));
                float logpt = ((lv == 0) ? p5 : p6) - lse;
                float pt  = __expf(logpt);
                float om  = 1.0f - pt;
                cls -= om*om*logpt;
                vc  += 1.0f;
            }
            if (lv == 0) {
                float sd = __fdividef(1.f, 1.f + __expf(-p4));
                sbg += sd*sd;
            }

            unsigned grp = __match_any_sync(FULLM, iv);
            if (iv >= 1) {
                int r3 = __reduce_add_sync(grp, __float2int_rn(p2*262144.f));        // 2^18
                int r4 = __reduce_add_sync(grp, __float2int_rn(p3*262144.f));
                int r5 = __reduce_add_sync(grp, __float2int_rn((p2*p2+p3*p3)*16384.f)); // 2^14
                if (lane == __ffs(grp)-1) {
                    int cnt = __popc(grp);
                    // sum of set-bit lane positions of grp
                    int S = __popc(grp & 0xAAAAAAAAu)
                          + 2*__popc(grp & 0xCCCCCCCCu)
                          + 4*__popc(grp & 0xF0F0F0F0u)
                          + 8*__popc(grp & 0xFF00FF00u)
                          + 16*__popc(grp & 0xFFFF0000u);
                    int w = tid*4 + j;             // w-coordinate of this pixel
                    int w0w = w - 4*lane;          // warp-base w for this j
                    float sumw = (float)(w0w*cnt + 4*S);
                    float* a = &s_acc[(iv-1)*6];
                    atomicAdd(a+0, (float)cnt);
                    atomicAdd(a+1, (2.0f/2047.0f)*sumw);
                    atomicAdd(a+2, yh*(float)cnt);
                    atomicAdd(a+3, (float)r3 * (1.f/262144.f));
                    atomicAdd(a+4, (float)r4 * (1.f/262144.f));
                    atomicAdd(a+5, (float)r5 * (1.f/16384.f));
                }
            }
        }
    }
    #pragma unroll
    for (int o = 16; o; o >>= 1) {
        cls += __shfl_down_sync(FULLM, cls, o);
        vc  += __shfl_down_sync(FULLM, vc,  o);
        sbg += __shfl_down_sync(FULLM, sbg, o);
    }
    if (lane == 0) {
        atomicAdd(&s_acc[42], cls);
        atomicAdd(&s_acc[43], vc);
        atomicAdd(&s_acc[44], sbg);
    }
    __syncthreads();
    if      (tid < 42) atomicAdd(&g_stat[b*42 + tid], s_acc[tid]);
    else if (tid < 45) atomicAdd(&g_batch[b*3 + tid - 42], s_acc[tid]);

    // ---- last-block-done: fused stage B ----
    __threadfence();
    __syncthreads();
    if (tid == 0) sLast = (atomicAdd(&g_semA, 1u) == NBLK_A-1);
    __syncthreads();
    if (sLast) {
        if (tid < NTASK) {
            int t = tid;
            float cnt  = __ldcg(&g_stat[t*6+0]);
            float s1   = __ldcg(&g_stat[t*6+1]);
            float s2   = __ldcg(&g_stat[t*6+2]);
            float s3   = __ldcg(&g_stat[t*6+3]);
            float s4   = __ldcg(&g_stat[t*6+4]);
            float s5   = __ldcg(&g_stat[t*6+5]);
            float pres = (cnt > 0.f) ? 1.f : 0.f;
            float cf   = fmaxf(cnt, 1.f);
            float m0 = s3/cf, m1 = s4/cf;
            g_task[t*8+0] = s1/cf;
            g_task[t*8+1] = s2/cf;
            g_task[t*8+2] = expf(10.f*m0);
            g_task[t*8+3] = expf(10.f*m1);
            g_task[t*8+4] = (s5 - cnt*(m0*m0 + m1*m1)) / (2.f*cf);
            g_task[t*8+5] = pres;
        }
        if (tid == 0) g_semA = 0;    // reset for next replay
    }
}

// ---------------- stage C: fg exact + bg 1/8-stratified weighted REDs ----------------
__global__ __launch_bounds__(256) void stageC(const float* __restrict__ pred,
                                              const int*  __restrict__ inst) {
    int b = blockIdx.y;
    int tid = threadIdx.x;
    __shared__ float4 sparam[8];   // indexed by iv; [0] = zeros
    if (tid < 8) {
        if (tid == 0) sparam[0] = make_float4(0.f,0.f,0.f,0.f);
        else {
            const float* tk = &g_task[(b*NID + tid-1)*8];
            sparam[tid] = make_float4(tk[0], tk[1], tk[2], tk[3]);
        }
    }
    __syncthreads();
    float cxr[NID], cyr[NID], sxr[NID], syr[NID];
    #pragma unroll
    for (int i = 0; i < NID; i++) {
        float4 q = sparam[i+1];
        cxr[i]=q.x; cyr[i]=q.y; sxr[i]=q.z; syr[i]=q.w;
    }

    const float* pb = pred + b*(CC*HW);
    unsigned* hb = g_hist + b*NID*NBINS*2;
    float sfg[NID] = {0.f,0.f,0.f,0.f,0.f,0.f,0.f};
    int base = blockIdx.x*2048;
    int lane = tid & 31;

    #pragma unroll
    for (int it = 0; it < 2; it++) {
        int px0 = base + it*1024 + tid*4;
        float4 q0v = *(const float4*)&pb[px0];
        float4 q1v = *(const float4*)&pb[HW+px0];
        float4 q4v = *(const float4*)&pb[4*HW+px0];
        int4   iv4 = *(const int4*)&inst[b*HW+px0];
        const float* c0 = (const float*)&q0v;
        const float* c1 = (const float*)&q1v;
        const float* c4 = (const float*)&q4v;
        const int*   ci = (const int*)&iv4;
        float yh = (1.0f/1023.0f)*(float)((base + it*1024) >> 10);

        #pragma unroll
        for (int j = 0; j < 4; j++) {
            float p0 = c0[j], p1 = c1[j];
            int iv = ci[j];
            float xw = (2.0f/2047.0f)*(float)(tid*4 + j);
            float t0 = __expf(2.f*p0);
            float t1 = __expf(2.f*p1);
            float ex = __fdividef(t0-1.f, t0+1.f) + xw;
            float ey = __fdividef(t1-1.f, t1+1.f) + yh;

            // ---- exact fg contribution for this pixel's own id ----
            if (iv >= 1) {
                float4 qq = sparam[iv];          // dynamic LDS.128
                float dx = ex - qq.x, dy = ey - qq.y;
                float d  = __expf(-(dx*dx*qq.z + dy*dy*qq.w));
                int bin  = min((int)((1.f - d)*(float)NBINS), NBINS-1);
                atomicAdd(hb + (iv-1)*(NBINS*2) + bin*2 + 1, 1u);
                float sd = __fdividef(1.f, 1.f + __expf(-c4[j]));
                float df = sd - d;
                float df2 = df*df;
                #pragma unroll
                for (int i = 0; i < NID; i++) sfg[i] += (iv == i+1) ? df2 : 0.f;
            }

            // ---- bg histogram: 1/8 stratified by pixel phase, weight 8 ----
            int phase = it*4 + j;                // compile-time constant per unrolled slot
            #pragma unroll
            for (int i = 0; i < NID; i++) {
                if (((phase + i) & 7) != 0) continue;   // 1 id per phase slot
                if (iv != i+1) {
                    float dx = ex - cxr[i], dy = ey - cyr[i];
                    float d  = __expf(-(dx*dx*sxr[i] + dy*dy*syr[i]));
                    int bin  = min((int)(d*(float)NBINS), NBINS-1);
                    atomicAdd(hb + i*(NBINS*2) + bin*2, 8u);
                }
            }
        }
    }
    // reduce sfg[7] across block
    __shared__ float sred[NID][8];
    #pragma unroll
    for (int i = 0; i < NID; i++) {
        float s = sfg[i];
        #pragma unroll
        for (int o = 16; o; o >>= 1) s += __shfl_down_sync(FULLM, s, o);
        if (lane == 0) sred[i][tid >> 5] = s;
    }
    __syncthreads();
    if (tid < NID) {
        float s = 0.f;
        #pragma unroll
        for (int w = 0; w < 8; w++) s += sred[tid][w];
        atomicAdd(&g_seedfg[b*NID + tid], s);
    }
}

// ---------------- stage D: Lovász scan + fused combine + self-clean ----------------
__global__ __launch_bounds__(256) void stageD(float* __restrict__ out) {
    int t = blockIdx.x;
    int tid = threadIdx.x;
    int lane = tid & 31, warp = tid >> 5;
    __shared__ bool sLast;
    bool present = (g_task[t*8+5] != 0.f);

    uint2* hh = (uint2*)(g_hist + t*(NBINS*2));   // .x=bg(w8) .y=fg
    const int BPT = NBINS/256;    // 4 bins/thread, descending chunk
    int hi = NBINS-1 - tid*BPT;

    unsigned lf = 0, lt = 0;
    uint2 cc[BPT];
    #pragma unroll
    for (int j = 0; j < BPT; j++) {
        cc[j] = hh[hi - j];
        hh[hi - j] = make_uint2(0u, 0u);          // self-clean for next replay
        lf += cc[j].y; lt += cc[j].x + cc[j].y;
    }

    __shared__ unsigned sWF[8], sWT[8];
    unsigned incF = lf, incT = lt;
    #pragma unroll
    for (int o = 1; o < 32; o <<= 1) {
        unsigned vF = __shfl_up_sync(FULLM, incF, o);
        unsigned vT = __shfl_up_sync(FULLM, incT, o);
        if (lane >= o) { incF += vF; incT += vT; }
    }
    if (lane == 31) { sWF[warp] = incF; sWT[warp] = incT; }
    __syncthreads();
    if (warp == 0 && lane < 8) {
        unsigned aF = sWF[lane], aT = sWT[lane];
        #pragma unroll
        for (int o = 1; o < 8; o <<= 1) {
            unsigned vF = __shfl_up_sync(0xffu, aF, o);
            unsigned vT = __shfl_up_sync(0xffu, aT, o);
            if (lane >= o) { aF += vF; aT += vT; }
        }
        sWF[lane] = aF; sWT[lane] = aT;
    }
    __syncthreads();
    unsigned F = (warp ? sWF[warp-1] : 0u) + incF - lf;
    unsigned T = (warp ? sWT[warp-1] : 0u) + incT - lt;

    float G = (float)sWF[7];      // exact fg total
    float loss = 0.f;
    if (present) {
        float jprev = 1.f - (G - (float)F) / (G + (float)(T - F));
        #pragma unroll
        for (int j = 0; j < BPT; j++) {
            int bin = hi - j;
            unsigned a = cc[j].y, c = cc[j].x + cc[j].y;
            if (c) {
                F += a; T += c;
                float jnew = 1.f - (G - (float)F) / (G + (float)(T - F));
                float e = ((float)bin + 0.5f) * (2.0f/(float)NBINS);
                loss += e * (jnew - jprev);
                jprev = jnew;
            }
        }
    }
    #pragma unroll
    for (int o = 16; o; o >>= 1) loss += __shfl_down_sync(FULLM, loss, o);
    __shared__ float sL[8];
    if (lane == 0) sL[warp] = loss;
    __syncthreads();
    if (tid == 0) {
        float v = 0.f;
        #pragma unroll
        for (int w = 0; w < 8; w++) v += sL[w];
        g_instl[t] = present ? v : 0.f;
    }

    // ---- last-block-done: fused final combine, then cleanup (ordered) ----
    __threadfence();
    __syncthreads();
    if (tid == 0) sLast = (atomicAdd(&g_semD, 1u) == NTASK-1);
    __syncthreads();
    if (sLast) {
        if (tid == 0) {
            float total = 0.f;
            for (int b2 = 0; b2 < BB; b2++) {
                float ps = 0.f, il = 0.f, vl = 0.f, sf = 0.f;
                for (int i = 0; i < NID; i++) {
                    int tt = b2*NID + i;
                    float p = g_task[tt*8+5];
                    ps += p;
                    il += __ldcg(&g_instl[tt]) * p;
                    vl += g_task[tt*8+4] * p;
                    sf += __ldcg(&g_seedfg[tt]) * p;
                }
                float obj = fmaxf(ps, 1.f);
                float seed_loss = (__ldcg(&g_batch[b2*3+2]) + 200.f*sf) / (float)HW;
                float loss_b = il/obj + 10.f*(vl/obj) + seed_loss;
                float cls_b  = __ldcg(&g_batch[b2*3+0]) / fmaxf(__ldcg(&g_batch[b2*3+1]), 1.f);
                total += loss_b + cls_b;
            }
            out[0] = total * 0.25f;
        }
        __syncthreads();   // combine reads complete before zeroing
        if (tid < NTASK*6) g_stat[tid]  = 0.f;
        if (tid < BB*3)    g_batch[tid] = 0.f;
        if (tid < NTASK)   g_seedfg[tid]= 0.f;
        if (tid == 0)      g_semD = 0;
    }
}

extern "C" void kernel_launch(void* const* d_in, const int* in_sizes, int n_in,
                              void* d_out, int out_size) {
    const float* pred = (const float*)d_in[0];
    const int*   inst = (const int*)  d_in[1];
    const int*   lab  = (const int*)  d_in[2];
    float* out = (float*)d_out;

    stageA <<<dim3(HW/2048, BB), 256>>>(pred, inst, lab);
    stageC <<<dim3(HW/2048, BB), 256>>>(pred, inst);
    stageD <<<NTASK, 256>>>(out);
}